// round 1
// baseline (speedup 1.0000x reference)
#include <cuda_runtime.h>
#include <math.h>

#define T_ 4
#define B_ 8
#define C_ 256
#define HID_ 1024
#define E_ 8
#define K_ 2
#define HW_ 196
#define NPIX_ 784   /* T_*HW_ */
#define EPS_ 1e-5f

// ---------------- device scratch (static, no allocation) ----------------
__device__ float g_X[B_ * C_];
__device__ int   g_topi[B_ * K_];
__device__ float g_topw[B_ * K_];
__device__ float g_S1[B_ * K_ * C_ * NPIX_];      // [slot][c][n]   (n = t*HW+hw)
__device__ float g_H [B_ * K_ * HID_ * NPIX_];    // [slot][o][n]
__device__ float g_S2[B_ * K_ * HID_ * NPIX_];    // [slot][o][n]
__device__ float g_O [B_ * K_ * C_ * NPIX_];      // [slot][c][n]  (topw folded in)

// ---------------- 1. per-(b,c) mean of x over (t,hw) ----------------
__global__ void reduce_x_kernel(const float* __restrict__ x) {
    int bc = blockIdx.x;             // b*C_ + c
    int b = bc / C_, c = bc % C_;
    float s = 0.f;
    for (int idx = threadIdx.x; idx < T_ * HW_; idx += blockDim.x) {
        int t = idx / HW_, hw = idx % HW_;
        s += x[((size_t)(t * B_ + b) * C_ + c) * HW_ + hw];
    }
    __shared__ float red[4];
    for (int o = 16; o; o >>= 1) s += __shfl_down_sync(0xFFFFFFFFu, s, o);
    if ((threadIdx.x & 31) == 0) red[threadIdx.x >> 5] = s;
    __syncthreads();
    if (threadIdx.x == 0) {
        float tot = red[0] + red[1] + red[2] + red[3];
        g_X[bc] = tot / (float)(T_ * HW_);
    }
}

// ---------------- 2. router: logits -> top-2 (softmax cancels) ----------------
__global__ void router_kernel(const float* __restrict__ rw, const float* __restrict__ rb,
                              const float* __restrict__ bg, const float* __restrict__ bb,
                              const float* __restrict__ bm, const float* __restrict__ bv) {
    __shared__ float lg[B_][E_];
    int tid = threadIdx.x;           // 64 threads
    int b = tid / E_, e = tid % E_;
    float dot = 0.f;
    for (int c = 0; c < C_; c++) dot += rw[e * C_ + c] * g_X[b * C_ + c];
    float val = dot + rb[e];
    float sc = bg[e] * rsqrtf(bv[e] + EPS_);
    lg[b][e] = (val - bm[e]) * sc + bb[e];
    __syncthreads();
    if (tid < B_) {
        float best = -1e30f, sec = -1e30f; int bi = 0, si = 0;
        for (int ee = 0; ee < E_; ee++) {
            float p = lg[tid][ee];
            if (p > best)      { sec = best; si = bi; best = p; bi = ee; }
            else if (p > sec)  { sec = p; si = ee; }
        }
        float r = expf(sec - best);            // <= 1
        float w0 = 1.f / (1.f + r);
        float w1 = r / (1.f + r);
        g_topi[tid * K_ + 0] = bi; g_topw[tid * K_ + 0] = w0;
        g_topi[tid * K_ + 1] = si; g_topw[tid * K_ + 1] = w1;
    }
}

// ---------------- 3. LIF layer 1: x -> binary spikes S1 ----------------
__global__ void spike1_kernel(const float* __restrict__ x, const float* __restrict__ taus) {
    int slot = blockIdx.y;
    int s = blockIdx.x * 256 + threadIdx.x;      // < C_*HW_ = 50176 (196 blocks exact)
    int c = s / HW_, hw = s % HW_;
    int b = slot / K_;
    float tau = taus[g_topi[slot]];
    float* out = g_S1 + (size_t)slot * C_ * NPIX_ + (size_t)c * NPIX_;
    float v = 0.f;
#pragma unroll
    for (int t = 0; t < T_; t++) {
        float xt = x[((size_t)(t * B_ + b) * C_ + c) * HW_ + hw];
        float h = v + (xt - v) / tau;
        float sp = (h >= 1.0f) ? 1.f : 0.f;
        out[t * HW_ + hw] = sp;
        v = h * (1.f - sp);
    }
}

// ---------------- 5. LIF layer 2: H -> binary spikes S2 ----------------
__global__ void spike2_kernel(const float* __restrict__ taus) {
    int slot = blockIdx.y;
    int s = blockIdx.x * 256 + threadIdx.x;      // < HID_*HW_ = 200704 (784 blocks exact)
    int o = s / HW_, hw = s % HW_;
    float tau = taus[g_topi[slot]];
    const float* hrow = g_H  + (size_t)slot * HID_ * NPIX_ + (size_t)o * NPIX_;
    float*       srow = g_S2 + (size_t)slot * HID_ * NPIX_ + (size_t)o * NPIX_;
    float v = 0.f;
#pragma unroll
    for (int t = 0; t < T_; t++) {
        float h = v + (hrow[t * HW_ + hw] - v) / tau;
        float sp = (h >= 1.0f) ? 1.f : 0.f;
        srow[t * HW_ + hw] = sp;
        v = h * (1.f - sp);
    }
}

// ---------------- 4/6. tiled GEMM with folded BN epilogue ----------------
// D[m][n] = bn( sum_k W[e][m][k] * Bsrc[slot][k][n] + bias[e][m] )  ( * topw if PHASE==2 )
// BM=64, BN=112, BK=16, 256 threads, per-thread micro-tile 4x7.
template<int MDIM, int KDIM, int PHASE>
__global__ void gemm_kernel(const float* __restrict__ W,
                            const float* __restrict__ bias,
                            const float* __restrict__ bng, const float* __restrict__ bnb,
                            const float* __restrict__ bnm, const float* __restrict__ bnv) {
    const int BM = 64, BN = 112, BK = 16;
    int slot = blockIdx.z;
    int m0 = blockIdx.y * BM;
    int n0 = blockIdx.x * BN;
    int e = g_topi[slot];
    const float* A = W + (size_t)e * MDIM * KDIM;
    const float* Bp = (PHASE == 1 ? g_S1 : g_S2) + (size_t)slot * KDIM * NPIX_;
    float*       Dst = (PHASE == 1 ? g_H  : g_O) + (size_t)slot * MDIM * NPIX_;

    __shared__ float As[BK][BM];
    __shared__ float Bs[BK][BN];

    int tid = threadIdx.x;
    int tm = tid >> 4;        // 0..15 -> m micro 4
    int tn = tid & 15;        // 0..15 -> n micro 7

    float acc[4][7];
#pragma unroll
    for (int i = 0; i < 4; i++)
#pragma unroll
        for (int j = 0; j < 7; j++) acc[i][j] = 0.f;

    int r = tid >> 2;               // 0..63   (A row)
    int kq = (tid & 3) * 4;         // 0,4,8,12

    for (int kt = 0; kt < KDIM; kt += BK) {
        // A tile: 64 x 16 (row-major K-minor in gmem) -> transposed As[k][m]
        float4 a4 = *(const float4*)&A[(size_t)(m0 + r) * KDIM + kt + kq];
        As[kq + 0][r] = a4.x; As[kq + 1][r] = a4.y;
        As[kq + 2][r] = a4.z; As[kq + 3][r] = a4.w;
        // B tile: 16 x 112
#pragma unroll
        for (int i = 0; i < 7; i++) {
            int idx = i * 256 + tid;
            int kk = idx / BN, nn = idx % BN;
            Bs[kk][nn] = Bp[(size_t)(kt + kk) * NPIX_ + n0 + nn];
        }
        __syncthreads();
#pragma unroll
        for (int k = 0; k < BK; k++) {
            float4 a = *(const float4*)&As[k][tm * 4];
            float av[4] = {a.x, a.y, a.z, a.w};
#pragma unroll
            for (int j = 0; j < 7; j++) {
                float bvv = Bs[k][tn * 7 + j];
#pragma unroll
                for (int i = 0; i < 4; i++) acc[i][j] += av[i] * bvv;
            }
        }
        __syncthreads();
    }

    float wslot = (PHASE == 2) ? g_topw[slot] : 1.f;
#pragma unroll
    for (int i = 0; i < 4; i++) {
        int mm = m0 + tm * 4 + i;
        int eo = e * MDIM + mm;
        float sc  = bng[eo] * rsqrtf(bnv[eo] + EPS_);
        float off = (bias[eo] - bnm[eo]) * sc + bnb[eo];
        float* drow = Dst + (size_t)mm * NPIX_ + n0 + tn * 7;
#pragma unroll
        for (int j = 0; j < 7; j++) {
            float val = acc[i][j] * sc + off;
            if (PHASE == 2) val *= wslot;
            drow[j] = val;
        }
    }
}

// ---------------- 7. combine: out = x + O[slot0] + O[slot1] ----------------
__global__ void combine_kernel(const float* __restrict__ x, float* __restrict__ out) {
    int i = blockIdx.x * 256 + threadIdx.x;   // < T*B*C*HW = 1605632 (6272 blocks exact)
    int hw = i % HW_;
    int c  = (i / HW_) % C_;
    int b  = (i / (HW_ * C_)) % B_;
    int t  = i / (HW_ * C_ * B_);
    int n  = t * HW_ + hw;
    const float* o0 = g_O + (size_t)(b * K_) * C_ * NPIX_ + (size_t)c * NPIX_ + n;
    out[i] = x[i] + o0[0] + o0[(size_t)C_ * NPIX_];
}

// ---------------- launch ----------------
extern "C" void kernel_launch(void* const* d_in, const int* in_sizes, int n_in,
                              void* d_out, int out_size) {
    const float* x        = (const float*)d_in[0];
    const float* router_w = (const float*)d_in[1];
    const float* router_b = (const float*)d_in[2];
    const float* rbn_g    = (const float*)d_in[3];
    const float* rbn_b    = (const float*)d_in[4];
    const float* rbn_m    = (const float*)d_in[5];
    const float* rbn_v    = (const float*)d_in[6];
    const float* fc1_w    = (const float*)d_in[7];
    const float* fc1_b    = (const float*)d_in[8];
    const float* bn1_g    = (const float*)d_in[9];
    const float* bn1_b    = (const float*)d_in[10];
    const float* bn1_m    = (const float*)d_in[11];
    const float* bn1_v    = (const float*)d_in[12];
    const float* fc2_w    = (const float*)d_in[13];
    const float* fc2_b    = (const float*)d_in[14];
    const float* bn2_g    = (const float*)d_in[15];
    const float* bn2_b    = (const float*)d_in[16];
    const float* bn2_m    = (const float*)d_in[17];
    const float* bn2_v    = (const float*)d_in[18];
    const float* taus     = (const float*)d_in[19];
    float* out = (float*)d_out;

    reduce_x_kernel<<<B_ * C_, 128>>>(x);
    router_kernel<<<1, 64>>>(router_w, router_b, rbn_g, rbn_b, rbn_m, rbn_v);
    spike1_kernel<<<dim3(C_ * HW_ / 256, B_ * K_), 256>>>(x, taus);
    gemm_kernel<HID_, C_, 1><<<dim3(NPIX_ / 112, HID_ / 64, B_ * K_), 256>>>(
        fc1_w, fc1_b, bn1_g, bn1_b, bn1_m, bn1_v);
    spike2_kernel<<<dim3(HID_ * HW_ / 256, B_ * K_), 256>>>(taus);
    gemm_kernel<C_, HID_, 2><<<dim3(NPIX_ / 112, C_ / 64, B_ * K_), 256>>>(
        fc2_w, fc2_b, bn2_g, bn2_b, bn2_m, bn2_v);
    combine_kernel<<<T_ * B_ * C_ * HW_ / 256, 256>>>(x, out);
}

// round 3
// speedup vs baseline: 2.2931x; 2.2931x over previous
#include <cuda_runtime.h>
#include <cuda_bf16.h>
#include <cstdint>
#include <math.h>

#define T_ 4
#define B_ 8
#define C_ 256
#define HID_ 1024
#define E_ 8
#define K_ 2
#define HW_ 196
#define NPIX_ 784   /* T_*HW_ */
#define EPS_ 1e-5f

// ======================= helpers =======================
__device__ __forceinline__ uint32_t smem_u32(const void* p) {
    uint32_t a;
    asm("{ .reg .u64 t; cvta.to.shared.u64 t, %1; cvt.u32.u64 %0, t; }" : "=r"(a) : "l"(p));
    return a;
}
__device__ __forceinline__ void cp_async16(uint32_t saddr, const void* gptr) {
    asm volatile("cp.async.cg.shared.global [%0], [%1], 16;" :: "r"(saddr), "l"(gptr) : "memory");
}
__device__ __forceinline__ void ldsm_x4(uint32_t& r0, uint32_t& r1, uint32_t& r2, uint32_t& r3,
                                        uint32_t addr) {
    asm volatile("ldmatrix.sync.aligned.m8n8.x4.shared.b16 {%0,%1,%2,%3}, [%4];"
                 : "=r"(r0), "=r"(r1), "=r"(r2), "=r"(r3) : "r"(addr));
}
__device__ __forceinline__ void ldsm_x2(uint32_t& r0, uint32_t& r1, uint32_t addr) {
    asm volatile("ldmatrix.sync.aligned.m8n8.x2.shared.b16 {%0,%1}, [%2];"
                 : "=r"(r0), "=r"(r1) : "r"(addr));
}
__device__ __forceinline__ void mma_bf16(float* c, const uint32_t* a, const uint32_t* b) {
    asm volatile("mma.sync.aligned.m16n8k16.row.col.f32.bf16.bf16.f32 "
                 "{%0,%1,%2,%3}, {%4,%5,%6,%7}, {%8,%9}, {%0,%1,%2,%3};"
                 : "+f"(c[0]), "+f"(c[1]), "+f"(c[2]), "+f"(c[3])
                 : "r"(a[0]), "r"(a[1]), "r"(a[2]), "r"(a[3]), "r"(b[0]), "r"(b[1]));
}

// ======================= device scratch (static) =======================
__device__ __align__(128) __nv_bfloat16 g_W1s[3u * E_ * HID_ * C_];     // [split][e][m][k]
__device__ __align__(128) __nv_bfloat16 g_W2s[3u * E_ * C_ * HID_];     // [split][e][m][k]
__device__ __align__(128) __nv_bfloat16 g_S1T[16u * NPIX_ * C_];        // [slot][n][c]
__device__ __align__(128) __nv_bfloat16 g_S2T[16u * NPIX_ * HID_];      // [slot][n][k]
__device__ __align__(128) float         g_O  [16u * C_ * NPIX_];        // [slot][c][t*196+hw]
__device__ float g_X[B_ * C_];
__device__ int   g_topi[B_ * K_];
__device__ float g_topw[B_ * K_];

// ======================= prep: fp32 -> bf16 x3 splits =======================
__global__ void prep_split_kernel(const float* __restrict__ w1, const float* __restrict__ w2) {
    const int NW = E_ * HID_ * C_;    // 2,097,152 (same count for both)
    int i = blockIdx.x * 256 + threadIdx.x;
    float w; __nv_bfloat16* dst; int idx;
    if (i < NW) { w = w1[i]; dst = g_W1s; idx = i; }
    else        { w = w2[i - NW]; dst = g_W2s; idx = i - NW; }
    __nv_bfloat16 hi = __float2bfloat16(w);
    float r1 = w - __bfloat162float(hi);
    __nv_bfloat16 mid = __float2bfloat16(r1);
    float r2 = r1 - __bfloat162float(mid);
    __nv_bfloat16 lo = __float2bfloat16(r2);
    dst[idx] = hi; dst[NW + idx] = mid; dst[2 * NW + idx] = lo;
}

// ======================= router path =======================
__global__ void reduce_x_kernel(const float* __restrict__ x) {
    int bc = blockIdx.x;
    int b = bc / C_, c = bc % C_;
    float s = 0.f;
    for (int idx = threadIdx.x; idx < T_ * HW_; idx += blockDim.x) {
        int t = idx / HW_, hw = idx % HW_;
        s += x[((size_t)(t * B_ + b) * C_ + c) * HW_ + hw];
    }
    __shared__ float red[4];
    for (int o = 16; o; o >>= 1) s += __shfl_down_sync(0xFFFFFFFFu, s, o);
    if ((threadIdx.x & 31) == 0) red[threadIdx.x >> 5] = s;
    __syncthreads();
    if (threadIdx.x == 0) g_X[bc] = (red[0] + red[1] + red[2] + red[3]) / (float)(T_ * HW_);
}

__global__ void router_kernel(const float* __restrict__ rw, const float* __restrict__ rb,
                              const float* __restrict__ bg, const float* __restrict__ bb,
                              const float* __restrict__ bm, const float* __restrict__ bv) {
    __shared__ float lg[B_][E_];
    int tid = threadIdx.x;
    int b = tid / E_, e = tid % E_;
    float dot = 0.f;
    for (int c = 0; c < C_; c++) dot += rw[e * C_ + c] * g_X[b * C_ + c];
    float val = dot + rb[e];
    float sc = bg[e] / sqrtf(bv[e] + EPS_);
    lg[b][e] = (val - bm[e]) * sc + bb[e];
    __syncthreads();
    if (tid < B_) {
        float best = -1e30f, sec = -1e30f; int bi = 0, si = 0;
        for (int ee = 0; ee < E_; ee++) {
            float p = lg[tid][ee];
            if (p > best)     { sec = best; si = bi; best = p; bi = ee; }
            else if (p > sec) { sec = p; si = ee; }
        }
        float r = expf(sec - best);
        g_topi[tid * K_ + 0] = bi; g_topw[tid * K_ + 0] = 1.f / (1.f + r);
        g_topi[tid * K_ + 1] = si; g_topw[tid * K_ + 1] = r / (1.f + r);
    }
}

// ======================= spike1: x -> S1T bf16 [slot][n=hw*4+t][c] =======================
__global__ void spike1_kernel(const float* __restrict__ x, const float* __restrict__ taus) {
    __shared__ float xs[4][32][50];
    __shared__ __align__(16) __nv_bfloat16 ss[196][36];   // 4-elem row pad (72B rows)
    int slot = blockIdx.z, hw0 = blockIdx.y * 49, c0 = blockIdx.x * 32;
    int b = slot >> 1;
    float tau = taus[g_topi[slot]];
    int tid = threadIdx.x;
    for (int q = tid; q < 4 * 32 * 49; q += 256) {
        int t = q / 1568; int r = q - t * 1568; int cl = r / 49; int hwl = r - cl * 49;
        xs[t][cl][hwl] = x[((size_t)(t * B_ + b) * C_ + c0 + cl) * HW_ + hw0 + hwl];
    }
    __syncthreads();
    for (int p = tid; p < 1568; p += 256) {
        int cl = p / 49, hwl = p - cl * 49;
        float v = 0.f;
#pragma unroll
        for (int t = 0; t < T_; t++) {
            float h = v + (xs[t][cl][hwl] - v) / tau;
            float sp = (h >= 1.0f) ? 1.f : 0.f;
            ss[hwl * 4 + t][cl] = __float2bfloat16(sp);
            v = h * (1.f - sp);
        }
    }
    __syncthreads();
    for (int q = tid; q < 196 * 8; q += 256) {
        int nl = q >> 3, u = q & 7;
        uint2 v = *(const uint2*)((const char*)ss + nl * 72 + u * 8);
        char* dst = (char*)(g_S1T + ((size_t)(slot * NPIX_) + hw0 * 4 + nl) * C_ + c0) + u * 8;
        *(uint2*)dst = v;
    }
}

// ======================= HMMA GEMM (bf16 splits, fused epilogues) =======================
// PHASE 1: D = W1*S1 -> bn1 -> LIF -> S2T bf16.   MDIM=1024, KDIM=256, 3 splits
// PHASE 2: D = W2*S2 -> bn2*topw -> g_O fp32.     MDIM=256,  KDIM=1024, 2 splits
template<int MDIM, int KDIM, int NSPLIT, int PHASE>
__global__ __launch_bounds__(128, 1)
void mma_kernel(const float* __restrict__ bias,
                const float* __restrict__ bng, const float* __restrict__ bnb,
                const float* __restrict__ bnm, const float* __restrict__ bnv,
                const float* __restrict__ taus) {
    constexpr int NCH = KDIM / 32;
    constexpr int NIT = NSPLIT * NCH;
    __shared__ __align__(16) __nv_bfloat16 sA[2][64 * 40];
    __shared__ __align__(16) __nv_bfloat16 sB[2][112 * 40];

    int tid = threadIdx.x, lane = tid & 31, wid = tid >> 5;
    int warpM = wid >> 1, warpN = wid & 1;
    int slot = blockIdx.z, m0 = blockIdx.y * 64, n0 = blockIdx.x * 112;
    int e = g_topi[slot];

    const __nv_bfloat16* Wbase = (PHASE == 1) ? g_W1s : g_W2s;
    const __nv_bfloat16* Bbase = ((PHASE == 1) ? g_S1T : g_S2T)
                                 + (size_t)slot * NPIX_ * KDIM + (size_t)n0 * KDIM;

    float acc[2][7][4];
#pragma unroll
    for (int mt = 0; mt < 2; mt++)
#pragma unroll
        for (int nt = 0; nt < 7; nt++)
#pragma unroll
            for (int cc = 0; cc < 4; cc++) acc[mt][nt][cc] = 0.f;

    auto load_stage = [&](int st, int it) {
        int s = it / NCH, kc = it % NCH;
        const __nv_bfloat16* Ag = Wbase + ((size_t)(s * E_ + e) * MDIM + m0) * KDIM + kc * 32;
        uint32_t sa = smem_u32(&sA[st][0]);
#pragma unroll
        for (int q = tid; q < 256; q += 128) {
            int r = q >> 2, cu = q & 3;
            cp_async16(sa + r * 80 + cu * 16, Ag + (size_t)r * KDIM + cu * 8);
        }
        const __nv_bfloat16* Bg = Bbase + kc * 32;
        uint32_t sb = smem_u32(&sB[st][0]);
        for (int q = tid; q < 448; q += 128) {
            int r = q >> 2, cu = q & 3;
            cp_async16(sb + r * 80 + cu * 16, Bg + (size_t)r * KDIM + cu * 8);
        }
        asm volatile("cp.async.commit_group;" ::: "memory");
    };

    load_stage(0, 0);
    for (int i = 0; i < NIT; i++) {
        if (i + 1 < NIT) {
            load_stage((i + 1) & 1, i + 1);
            asm volatile("cp.async.wait_group 1;" ::: "memory");
        } else {
            asm volatile("cp.async.wait_group 0;" ::: "memory");
        }
        __syncthreads();
        int st = i & 1;
        uint32_t aw = smem_u32(&sA[st][0]) + (warpM * 32 + (lane & 15)) * 80 + (lane >> 4) * 16;
        uint32_t bw = smem_u32(&sB[st][0]) + (warpN * 56 + (lane & 7)) * 80 + ((lane >> 3) & 1) * 16;
#pragma unroll
        for (int kst = 0; kst < 2; kst++) {
            uint32_t a[2][4], b[7][2];
#pragma unroll
            for (int mt = 0; mt < 2; mt++)
                ldsm_x4(a[mt][0], a[mt][1], a[mt][2], a[mt][3], aw + mt * 16 * 80 + kst * 32);
#pragma unroll
            for (int nt = 0; nt < 7; nt++)
                ldsm_x2(b[nt][0], b[nt][1], bw + nt * 8 * 80 + kst * 32);
#pragma unroll
            for (int mt = 0; mt < 2; mt++)
#pragma unroll
                for (int nt = 0; nt < 7; nt++)
                    mma_bf16(acc[mt][nt], a[mt], b[nt]);
        }
        __syncthreads();
    }

    // ---- epilogue ----
    int rb = lane >> 2, q = lane & 3;
    float scv[4], ofv[4];
#pragma unroll
    for (int j = 0; j < 4; j++) {
        int m = m0 + warpM * 32 + (j >> 1) * 16 + (j & 1) * 8 + rb;
        int eo = e * MDIM + m;
        scv[j] = bng[eo] / sqrtf(bnv[eo] + EPS_);
        ofv[j] = (bias[eo] - bnm[eo]) * scv[j] + bnb[eo];
    }

    if (PHASE == 1) {
        float tau = taus[e];
#pragma unroll
        for (int mt = 0; mt < 2; mt++)
#pragma unroll
            for (int h = 0; h < 2; h++) {
                int j = mt * 2 + h;
                int m = m0 + warpM * 32 + mt * 16 + h * 8 + rb;
                __nv_bfloat16* dcol = g_S2T + (size_t)slot * NPIX_ * HID_ + m;
#pragma unroll
                for (int nt = 0; nt < 7; nt++) {
                    float x0 = acc[mt][nt][h * 2 + 0] * scv[j] + ofv[j];
                    float x1 = acc[mt][nt][h * 2 + 1] * scv[j] + ofv[j];
                    // phase A: t0,t1 starting from v=0 (valid on even q)
                    float h0 = 0.f + (x0 - 0.f) / tau;
                    float s0 = (h0 >= 1.f) ? 1.f : 0.f;
                    float v1 = h0 * (1.f - s0);
                    float h1 = v1 + (x1 - v1) / tau;
                    float s1 = (h1 >= 1.f) ? 1.f : 0.f;
                    float vA = h1 * (1.f - s1);
                    // pass membrane to odd q partner
                    float vin = __shfl_sync(0xFFFFFFFFu, vA, lane & ~1);
                    // phase B: t2,t3 (valid on odd q)
                    float h2 = vin + (x0 - vin) / tau;
                    float s2 = (h2 >= 1.f) ? 1.f : 0.f;
                    float v3 = h2 * (1.f - s2);
                    float h3 = v3 + (x1 - v3) / tau;
                    float s3 = (h3 >= 1.f) ? 1.f : 0.f;
                    float o0 = (q & 1) ? s2 : s0;
                    float o1 = (q & 1) ? s3 : s1;
                    int n = n0 + warpN * 56 + nt * 8 + q * 2;
                    dcol[(size_t)n * HID_]       = __float2bfloat16(o0);
                    dcol[(size_t)(n + 1) * HID_] = __float2bfloat16(o1);
                }
            }
    } else {
        float w = g_topw[slot];
#pragma unroll
        for (int j = 0; j < 4; j++) { scv[j] *= w; ofv[j] *= w; }
#pragma unroll
        for (int mt = 0; mt < 2; mt++)
#pragma unroll
            for (int h = 0; h < 2; h++) {
                int j = mt * 2 + h;
                int m = m0 + warpM * 32 + mt * 16 + h * 8 + rb;
                float* dst = g_O + (size_t)(slot * C_ + m) * NPIX_;
#pragma unroll
                for (int nt = 0; nt < 7; nt++) {
#pragma unroll
                    for (int col = 0; col < 2; col++) {
                        int n = n0 + warpN * 56 + nt * 8 + q * 2 + col;
                        dst[(n & 3) * HW_ + (n >> 2)] = acc[mt][nt][h * 2 + col] * scv[j] + ofv[j];
                    }
                }
            }
    }
}

// ======================= combine =======================
__global__ void combine_kernel(const float* __restrict__ x, float* __restrict__ out) {
    int i = blockIdx.x * 256 + threadIdx.x;
    int hw = i % HW_;
    int c  = (i / HW_) % C_;
    int b  = (i / (HW_ * C_)) % B_;
    int t  = i / (HW_ * C_ * B_);
    size_t o0 = ((size_t)(b * K_) * C_ + c) * NPIX_ + t * HW_ + hw;
    out[i] = x[i] + g_O[o0] + g_O[o0 + (size_t)C_ * NPIX_];
}

// ======================= launch =======================
extern "C" void kernel_launch(void* const* d_in, const int* in_sizes, int n_in,
                              void* d_out, int out_size) {
    const float* x        = (const float*)d_in[0];
    const float* router_w = (const float*)d_in[1];
    const float* router_b = (const float*)d_in[2];
    const float* rbn_g    = (const float*)d_in[3];
    const float* rbn_b    = (const float*)d_in[4];
    const float* rbn_m    = (const float*)d_in[5];
    const float* rbn_v    = (const float*)d_in[6];
    const float* fc1_w    = (const float*)d_in[7];
    const float* fc1_b    = (const float*)d_in[8];
    const float* bn1_g    = (const float*)d_in[9];
    const float* bn1_b    = (const float*)d_in[10];
    const float* bn1_m    = (const float*)d_in[11];
    const float* bn1_v    = (const float*)d_in[12];
    const float* fc2_w    = (const float*)d_in[13];
    const float* fc2_b    = (const float*)d_in[14];
    const float* bn2_g    = (const float*)d_in[15];
    const float* bn2_b    = (const float*)d_in[16];
    const float* bn2_m    = (const float*)d_in[17];
    const float* bn2_v    = (const float*)d_in[18];
    const float* taus     = (const float*)d_in[19];
    float* out = (float*)d_out;

    prep_split_kernel<<<2 * E_ * HID_ * C_ / 256, 256>>>(fc1_w, fc2_w);
    reduce_x_kernel<<<B_ * C_, 128>>>(x);
    router_kernel<<<1, 64>>>(router_w, router_b, rbn_g, rbn_b, rbn_m, rbn_v);
    spike1_kernel<<<dim3(C_ / 32, 4, B_ * K_), 256>>>(x, taus);
    mma_kernel<HID_, C_, 3, 1><<<dim3(7, HID_ / 64, B_ * K_), 128>>>(
        fc1_b, bn1_g, bn1_b, bn1_m, bn1_v, taus);
    mma_kernel<C_, HID_, 2, 2><<<dim3(7, C_ / 64, B_ * K_), 128>>>(
        fc2_b, bn2_g, bn2_b, bn2_m, bn2_v, taus);
    combine_kernel<<<T_ * B_ * C_ * HW_ / 256, 256>>>(x, out);
}

// round 4
// speedup vs baseline: 2.9285x; 1.2771x over previous
#include <cuda_runtime.h>
#include <cuda_fp16.h>
#include <cstdint>
#include <math.h>

#define T_ 4
#define B_ 8
#define C_ 256
#define HID_ 1024
#define E_ 8
#define K_ 2
#define HW_ 196
#define NPIX_ 784   /* T_*HW_ */
#define EPS_ 1e-5f

// ======================= helpers =======================
__device__ __forceinline__ uint32_t smem_u32(const void* p) {
    uint32_t a;
    asm("{ .reg .u64 t; cvta.to.shared.u64 t, %1; cvt.u32.u64 %0, t; }" : "=r"(a) : "l"(p));
    return a;
}
__device__ __forceinline__ void cp_async16(uint32_t saddr, const void* gptr) {
    asm volatile("cp.async.cg.shared.global [%0], [%1], 16;" :: "r"(saddr), "l"(gptr) : "memory");
}
__device__ __forceinline__ void ldsm_x4(uint32_t& r0, uint32_t& r1, uint32_t& r2, uint32_t& r3,
                                        uint32_t addr) {
    asm volatile("ldmatrix.sync.aligned.m8n8.x4.shared.b16 {%0,%1,%2,%3}, [%4];"
                 : "=r"(r0), "=r"(r1), "=r"(r2), "=r"(r3) : "r"(addr));
}
__device__ __forceinline__ void mma_f16(float* c, const uint32_t* a, const uint32_t* b) {
    asm volatile("mma.sync.aligned.m16n8k16.row.col.f32.f16.f16.f32 "
                 "{%0,%1,%2,%3}, {%4,%5,%6,%7}, {%8,%9}, {%0,%1,%2,%3};"
                 : "+f"(c[0]), "+f"(c[1]), "+f"(c[2]), "+f"(c[3])
                 : "r"(a[0]), "r"(a[1]), "r"(a[2]), "r"(a[3]), "r"(b[0]), "r"(b[1]));
}

// ======================= device scratch (static) =======================
__device__ __align__(128) __half g_W1s[2u * E_ * HID_ * C_];     // [split][e][m][k]
__device__ __align__(128) __half g_W2s[2u * E_ * C_ * HID_];     // [split][e][m][k]
__device__ __align__(128) __half g_S1T[16u * NPIX_ * C_];        // [slot][n][c]
__device__ __align__(128) __half g_S2T[16u * NPIX_ * HID_];      // [slot][n][k]
__device__ __align__(128) float  g_O  [16u * C_ * NPIX_];        // [slot][c][t][hw]
__device__ float g_X[B_ * C_];
__device__ int   g_topi[B_ * K_];
__device__ float g_topw[B_ * K_];

// ======================= prep: fp32 -> 2x fp16 splits =======================
__global__ void prep_split_kernel(const float* __restrict__ w1, const float* __restrict__ w2) {
    const int NW = E_ * HID_ * C_;    // 2,097,152 each
    int i4 = (blockIdx.x * 256 + threadIdx.x) * 4;
    const float* src; __half* dst; int idx;
    if (i4 < NW) { src = w1 + i4;        dst = g_W1s; idx = i4; }
    else         { src = w2 + (i4 - NW); dst = g_W2s; idx = i4 - NW; }
    float4 wv = *(const float4*)src;
    float w[4] = {wv.x, wv.y, wv.z, wv.w};
    uint16_t h[4], m[4];
#pragma unroll
    for (int j = 0; j < 4; j++) {
        __half hi = __float2half(w[j]);
        __half mi = __float2half(w[j] - __half2float(hi));
        h[j] = __half_as_ushort(hi);
        m[j] = __half_as_ushort(mi);
    }
    uint2 hp = make_uint2((uint32_t)h[0] | ((uint32_t)h[1] << 16),
                          (uint32_t)h[2] | ((uint32_t)h[3] << 16));
    uint2 mp = make_uint2((uint32_t)m[0] | ((uint32_t)m[1] << 16),
                          (uint32_t)m[2] | ((uint32_t)m[3] << 16));
    *(uint2*)&dst[idx] = hp;
    *(uint2*)&dst[NW + idx] = mp;
}

// ======================= router path =======================
__global__ void reduce_x_kernel(const float* __restrict__ x) {
    int bc = blockIdx.x;
    int b = bc / C_, c = bc % C_;
    float s = 0.f;
    for (int idx = threadIdx.x; idx < T_ * HW_; idx += blockDim.x) {
        int t = idx / HW_, hw = idx % HW_;
        s += x[((size_t)(t * B_ + b) * C_ + c) * HW_ + hw];
    }
    __shared__ float red[4];
    for (int o = 16; o; o >>= 1) s += __shfl_down_sync(0xFFFFFFFFu, s, o);
    if ((threadIdx.x & 31) == 0) red[threadIdx.x >> 5] = s;
    __syncthreads();
    if (threadIdx.x == 0) g_X[bc] = (red[0] + red[1] + red[2] + red[3]) / (float)(T_ * HW_);
}

__global__ void router_kernel(const float* __restrict__ rw, const float* __restrict__ rb,
                              const float* __restrict__ bg, const float* __restrict__ bb,
                              const float* __restrict__ bm, const float* __restrict__ bv) {
    __shared__ float lg[B_][E_];
    int tid = threadIdx.x;
    int b = tid / E_, e = tid % E_;
    float dot = 0.f;
    for (int c = 0; c < C_; c++) dot += rw[e * C_ + c] * g_X[b * C_ + c];
    float val = dot + rb[e];
    float sc = bg[e] / sqrtf(bv[e] + EPS_);
    lg[b][e] = (val - bm[e]) * sc + bb[e];
    __syncthreads();
    if (tid < B_) {
        float best = -1e30f, sec = -1e30f; int bi = 0, si = 0;
        for (int ee = 0; ee < E_; ee++) {
            float p = lg[tid][ee];
            if (p > best)     { sec = best; si = bi; best = p; bi = ee; }
            else if (p > sec) { sec = p; si = ee; }
        }
        float r = expf(sec - best);
        g_topi[tid * K_ + 0] = bi; g_topw[tid * K_ + 0] = 1.f / (1.f + r);
        g_topi[tid * K_ + 1] = si; g_topw[tid * K_ + 1] = r / (1.f + r);
    }
}

// ======================= spike1: x -> S1T fp16 [slot][n=hw*4+t][c] =======================
__global__ void spike1_kernel(const float* __restrict__ x, const float* __restrict__ taus) {
    __shared__ __half ss[32][198];   // [cl][nl], pitch 198 halves (99 words, odd -> no conflicts)
    int slot = blockIdx.z, hw0 = blockIdx.y * 49, c0 = blockIdx.x * 32;
    int b = slot >> 1;
    float tau = taus[g_topi[slot]];
    int tid = threadIdx.x;
    const size_t TSTRIDE = (size_t)B_ * C_ * HW_;
    for (int p = tid; p < 32 * 49; p += 256) {
        int cl = p / 49, hwl = p - cl * 49;
        const float* xp = x + ((size_t)(b * C_) + c0 + cl) * HW_ + hw0 + hwl;
        float v = 0.f;
#pragma unroll
        for (int t = 0; t < T_; t++) {
            float xt = xp[t * TSTRIDE];
            float h = v + (xt - v) / tau;
            float sp = (h >= 1.0f) ? 1.f : 0.f;
            ss[cl][hwl * 4 + t] = __float2half(sp);
            v = h * (1.f - sp);
        }
    }
    __syncthreads();
    // pack & write: each q handles a (c-pair, n) cell -> one 4B store, coalesced
    for (int q = tid; q < 196 * 16; q += 256) {
        int nl = q >> 4, pa = q & 15;
        uint32_t packed = (uint32_t)__half_as_ushort(ss[pa * 2][nl])
                        | ((uint32_t)__half_as_ushort(ss[pa * 2 + 1][nl]) << 16);
        *(uint32_t*)&g_S1T[((size_t)slot * NPIX_ + hw0 * 4 + nl) * C_ + c0 + pa * 2] = packed;
    }
}

// ======================= HMMA GEMM: 128x112 CTA tile, 2 fp16 splits share B =======================
// PHASE 1: D = W1*S1 -> bn1 -> LIF -> S2T fp16.   MDIM=1024, KDIM=256
// PHASE 2: D = W2*S2 -> bn2*topw -> g_O (smem-transposed, coalesced). MDIM=256, KDIM=1024
template<int MDIM, int KDIM, int PHASE>
__global__ __launch_bounds__(256, 2)
void mma_kernel(const float* __restrict__ bias,
                const float* __restrict__ bng, const float* __restrict__ bnb,
                const float* __restrict__ bnm, const float* __restrict__ bnv,
                const float* __restrict__ taus) {
    constexpr int NIT = KDIM / 32;
    constexpr int STAGE = 29440;          // A0(10240) + A1(10240) + B(8960)
    extern __shared__ __align__(16) char smem[];
    uint32_t sbase = smem_u32(smem);

    int tid = threadIdx.x, lane = tid & 31, wid = tid >> 5;
    int warpM = wid >> 1, warpN = wid & 1;          // 4 x 2 warps -> 128 x 112
    int slot = blockIdx.z, m0 = blockIdx.y * 128, n0 = blockIdx.x * 112;
    int e = g_topi[slot];

    const __half* Wbase = (PHASE == 1) ? g_W1s : g_W2s;
    const __half* Bbase = ((PHASE == 1) ? g_S1T : g_S2T)
                          + (size_t)slot * NPIX_ * KDIM + (size_t)n0 * KDIM;

    float acc[2][7][4];
#pragma unroll
    for (int mt = 0; mt < 2; mt++)
#pragma unroll
        for (int nt = 0; nt < 7; nt++)
#pragma unroll
            for (int cc = 0; cc < 4; cc++) acc[mt][nt][cc] = 0.f;

    auto load_stage = [&](int st, int kc) {
        uint32_t sb = sbase + st * STAGE;
#pragma unroll
        for (int q = tid; q < 1024; q += 256) {       // A: 2 splits x 128 rows x 4 chunks
            int sp = q >> 9, r = (q >> 2) & 127, cu = q & 3;
            const __half* src = Wbase + ((size_t)(sp * E_ + e) * MDIM + m0 + r) * KDIM
                              + kc * 32 + cu * 8;
            cp_async16(sb + sp * 10240 + r * 80 + cu * 16, src);
        }
        for (int q = tid; q < 448; q += 256) {        // B: 112 rows x 4 chunks
            int r = q >> 2, cu = q & 3;
            cp_async16(sb + 20480 + r * 80 + cu * 16,
                       Bbase + (size_t)r * KDIM + kc * 32 + cu * 8);
        }
        asm volatile("cp.async.commit_group;" ::: "memory");
    };

    load_stage(0, 0);
    load_stage(1, 1);

    for (int i = 0; i < NIT; i++) {
        if (i + 1 < NIT) asm volatile("cp.async.wait_group 1;" ::: "memory");
        else             asm volatile("cp.async.wait_group 0;" ::: "memory");
        __syncthreads();
        if (i + 2 < NIT) load_stage((i + 2) % 3, i + 2);   // buffer (i-1)%3 is free

        int st = i % 3;
        uint32_t bw = sbase + st * STAGE + 20480
                    + (warpN * 56 + (lane & 7)) * 80 + ((lane >> 3) & 1) * 16
                    + (lane >> 4) * 32;
        uint32_t b[7][4];
#pragma unroll
        for (int nt = 0; nt < 7; nt++)
            ldsm_x4(b[nt][0], b[nt][1], b[nt][2], b[nt][3], bw + nt * 640);
#pragma unroll
        for (int sp = 0; sp < 2; sp++) {
            uint32_t abase = sbase + st * STAGE + sp * 10240
                           + (warpM * 32 + (lane & 15)) * 80 + (lane >> 4) * 16;
#pragma unroll
            for (int kst = 0; kst < 2; kst++) {
                uint32_t a[2][4];
                ldsm_x4(a[0][0], a[0][1], a[0][2], a[0][3], abase + kst * 32);
                ldsm_x4(a[1][0], a[1][1], a[1][2], a[1][3], abase + 16 * 80 + kst * 32);
#pragma unroll
                for (int nt = 0; nt < 7; nt++) {
                    mma_f16(acc[0][nt], a[0], &b[nt][kst * 2]);
                    mma_f16(acc[1][nt], a[1], &b[nt][kst * 2]);
                }
            }
        }
    }

    // ---- epilogue ----
    int rb = lane >> 2, q = lane & 3;
    float scv[4], ofv[4];
#pragma unroll
    for (int j = 0; j < 4; j++) {
        int m = m0 + warpM * 32 + (j >> 1) * 16 + (j & 1) * 8 + rb;
        int eo = e * MDIM + m;
        scv[j] = bng[eo] / sqrtf(bnv[eo] + EPS_);
        ofv[j] = (bias[eo] - bnm[eo]) * scv[j] + bnb[eo];
    }

    if (PHASE == 1) {
        float tau = taus[e];
#pragma unroll
        for (int mt = 0; mt < 2; mt++)
#pragma unroll
            for (int h = 0; h < 2; h++) {
                int j = mt * 2 + h;
                int m = m0 + warpM * 32 + mt * 16 + h * 8 + rb;
                __half* dcol = g_S2T + (size_t)slot * NPIX_ * HID_ + m;
#pragma unroll
                for (int nt = 0; nt < 7; nt++) {
                    float x0 = acc[mt][nt][h * 2 + 0] * scv[j] + ofv[j];
                    float x1 = acc[mt][nt][h * 2 + 1] * scv[j] + ofv[j];
                    // phase A: t0,t1 from v=0 (valid on even q)
                    float h0 = x0 / tau;
                    float s0 = (h0 >= 1.f) ? 1.f : 0.f;
                    float v1 = h0 * (1.f - s0);
                    float h1 = v1 + (x1 - v1) / tau;
                    float s1 = (h1 >= 1.f) ? 1.f : 0.f;
                    float vA = h1 * (1.f - s1);
                    float vin = __shfl_sync(0xFFFFFFFFu, vA, lane & ~1);
                    // phase B: t2,t3 (valid on odd q)
                    float h2 = vin + (x0 - vin) / tau;
                    float s2 = (h2 >= 1.f) ? 1.f : 0.f;
                    float v3 = h2 * (1.f - s2);
                    float h3 = v3 + (x1 - v3) / tau;
                    float s3 = (h3 >= 1.f) ? 1.f : 0.f;
                    float o0 = (q & 1) ? s2 : s0;
                    float o1 = (q & 1) ? s3 : s1;
                    int n = n0 + warpN * 56 + nt * 8 + q * 2;
                    dcol[(size_t)n * HID_]       = __float2half(o0);
                    dcol[(size_t)(n + 1) * HID_] = __float2half(o1);
                }
            }
    } else {
        float w = g_topw[slot];
        float* sP = (float*)smem;                 // reuse pipeline smem: 128 x pitch113 fp32
        __syncthreads();                          // all warps done with ldsm
#pragma unroll
        for (int mt = 0; mt < 2; mt++)
#pragma unroll
            for (int h = 0; h < 2; h++) {
                int j = mt * 2 + h;
                int ml = warpM * 32 + mt * 16 + h * 8 + rb;
                float scw = scv[j] * w, offw = ofv[j] * w;
#pragma unroll
                for (int nt = 0; nt < 7; nt++) {
#pragma unroll
                    for (int col = 0; col < 2; col++) {
                        int nl = warpN * 56 + nt * 8 + q * 2 + col;
                        sP[ml * 113 + nl] = acc[mt][nt][h * 2 + col] * scw + offw;
                    }
                }
            }
        __syncthreads();
        int hw0 = blockIdx.x * 28;
        for (int p = tid; p < 512; p += 256) {
            int m = p >> 2, t = p & 3;
            float* dst = g_O + ((size_t)((slot * C_ + m0 + m) * 4 + t)) * HW_ + hw0;
            const float* srow = sP + m * 113 + t;
#pragma unroll
            for (int hwl = 0; hwl < 28; hwl++) dst[hwl] = srow[hwl * 4];
        }
    }
}

// ======================= combine =======================
__global__ void combine_kernel(const float* __restrict__ x, float* __restrict__ out) {
    int i = blockIdx.x * 256 + threadIdx.x;
    int hw = i % HW_;
    int c  = (i / HW_) % C_;
    int b  = (i / (HW_ * C_)) % B_;
    int t  = i / (HW_ * C_ * B_);
    size_t o0 = ((size_t)(b * K_) * C_ + c) * NPIX_ + t * HW_ + hw;
    out[i] = x[i] + g_O[o0] + g_O[o0 + (size_t)C_ * NPIX_];
}

// ======================= launch =======================
extern "C" void kernel_launch(void* const* d_in, const int* in_sizes, int n_in,
                              void* d_out, int out_size) {
    const float* x        = (const float*)d_in[0];
    const float* router_w = (const float*)d_in[1];
    const float* router_b = (const float*)d_in[2];
    const float* rbn_g    = (const float*)d_in[3];
    const float* rbn_b    = (const float*)d_in[4];
    const float* rbn_m    = (const float*)d_in[5];
    const float* rbn_v    = (const float*)d_in[6];
    const float* fc1_w    = (const float*)d_in[7];
    const float* fc1_b    = (const float*)d_in[8];
    const float* bn1_g    = (const float*)d_in[9];
    const float* bn1_b    = (const float*)d_in[10];
    const float* bn1_m    = (const float*)d_in[11];
    const float* bn1_v    = (const float*)d_in[12];
    const float* fc2_w    = (const float*)d_in[13];
    const float* fc2_b    = (const float*)d_in[14];
    const float* bn2_g    = (const float*)d_in[15];
    const float* bn2_b    = (const float*)d_in[16];
    const float* bn2_m    = (const float*)d_in[17];
    const float* bn2_v    = (const float*)d_in[18];
    const float* taus     = (const float*)d_in[19];
    float* out = (float*)d_out;

    const int SMEM_MMA = 3 * 29440;   // 88320
    cudaFuncSetAttribute(mma_kernel<HID_, C_, 1>,
                         cudaFuncAttributeMaxDynamicSharedMemorySize, SMEM_MMA);
    cudaFuncSetAttribute(mma_kernel<C_, HID_, 2>,
                         cudaFuncAttributeMaxDynamicSharedMemorySize, SMEM_MMA);

    prep_split_kernel<<<2 * E_ * HID_ * C_ / 1024, 256>>>(fc1_w, fc2_w);
    reduce_x_kernel<<<B_ * C_, 128>>>(x);
    router_kernel<<<1, 64>>>(router_w, router_b, rbn_g, rbn_b, rbn_m, rbn_v);
    spike1_kernel<<<dim3(C_ / 32, 4, B_ * K_), 256>>>(x, taus);
    mma_kernel<HID_, C_, 1><<<dim3(7, HID_ / 128, B_ * K_), 256, SMEM_MMA>>>(
        fc1_b, bn1_g, bn1_b, bn1_m, bn1_v, taus);
    mma_kernel<C_, HID_, 2><<<dim3(7, C_ / 128, B_ * K_), 256, SMEM_MMA>>>(
        fc2_b, bn2_g, bn2_b, bn2_m, bn2_v, taus);
    combine_kernel<<<T_ * B_ * C_ * HW_ / 256, 256>>>(x, out);
}